// round 7
// baseline (speedup 1.0000x reference)
#include <cuda_runtime.h>
#include <cuda_bf16.h>

// ---------------------------------------------------------------------------
// SageConv: out = relu([x@Wl + bl | (scatter_sum(val*x[col] -> row))@Wn + bn])
// N=100000 nodes, E=1.6M edges, D_IN=D_OUT=128.
//
// Round 7: overlap the L2-bound pull with the FMA-bound local GEMM inside one
// persistent mega-kernel (warp specialization + device-wide barrier):
//   CSR build (6 small kernels), then mega_kernel (148 CTAs, all resident):
//     phase 1: warps 0-3 local GEMM (x@Wl) | warps 4-7 pull rows (atomic queue)
//              GEMM warps join the pull queue when their tiles are done
//     device barrier (spin counter; zeroed per call by k_zero_deg)
//     phase 2: all 8 warps neigh GEMM (agg@Wn)
// ---------------------------------------------------------------------------

#define NN 100000
#define EE 1600000
#define D 128

__device__ __align__(16) float g_agg[NN * D];
__device__ int g_deg[NN];
__device__ int g_off[NN + 1];
__device__ int g_cur[NN];
__device__ int g_part[512];   // block partials; requires ceil(NN/256) <= 512
__device__ __align__(8) unsigned long long g_csr[EE];  // hi32=val, lo32=col
__device__ int g_bar;      // device-wide barrier counter (zeroed per call)
__device__ int g_rowcur;   // pull row work queue cursor (zeroed per call)

// ---------------------------------------------------------------------------
__global__ void k_zero_deg(int n) {
    if (blockIdx.x == 0 && threadIdx.x == 0) { g_bar = 0; g_rowcur = 0; }
    for (int i = blockIdx.x * blockDim.x + threadIdx.x; i < n;
         i += gridDim.x * blockDim.x)
        g_deg[i] = 0;
}

__global__ void k_hist(const int* __restrict__ erow, int E) {
    for (int e = blockIdx.x * blockDim.x + threadIdx.x; e < E;
         e += gridDim.x * blockDim.x)
        atomicAdd(&g_deg[__ldg(erow + e)], 1);
}

__global__ void k_partial(int n) {
    __shared__ int s[256];
    int i = blockIdx.x * 256 + threadIdx.x;
    s[threadIdx.x] = (i < n) ? g_deg[i] : 0;
    __syncthreads();
    for (int d = 128; d > 0; d >>= 1) {
        if (threadIdx.x < d) s[threadIdx.x] += s[threadIdx.x + d];
        __syncthreads();
    }
    if (threadIdx.x == 0) g_part[blockIdx.x] = s[0];
}

__global__ void k_scan(int nb) {   // 1 block, 512 threads; nb <= 512
    __shared__ int s[512];
    int t = threadIdx.x;
    s[t] = (t < nb) ? g_part[t] : 0;
    __syncthreads();
    for (int d = 1; d < 512; d <<= 1) {
        int v = (t >= d) ? s[t - d] : 0;
        __syncthreads();
        s[t] += v;
        __syncthreads();
    }
    int excl = (t > 0) ? s[t - 1] : 0;
    if (t < nb) g_part[t] = excl;
}

__global__ void k_offsets(int n) {
    __shared__ int s[256];
    int t = threadIdx.x;
    int i = blockIdx.x * 256 + t;
    int dg = (i < n) ? g_deg[i] : 0;
    s[t] = dg;
    __syncthreads();
    for (int d = 1; d < 256; d <<= 1) {
        int v = (t >= d) ? s[t - d] : 0;
        __syncthreads();
        s[t] += v;
        __syncthreads();
    }
    int incl = s[t];
    int base = g_part[blockIdx.x];
    if (i < n) {
        int off = base + incl - dg;
        g_off[i] = off;
        g_cur[i] = off;
        if (i == n - 1) g_off[n] = base + incl;
    }
}

__global__ void k_bin(const int* __restrict__ erow,
                      const int* __restrict__ ecol,
                      const float* __restrict__ eval_, int E) {
    for (int e = blockIdx.x * blockDim.x + threadIdx.x; e < E;
         e += gridDim.x * blockDim.x) {
        int r = __ldg(erow + e);
        int c = __ldg(ecol + e);
        float v = __ldg(eval_ + e);
        int pos = atomicAdd(&g_cur[r], 1);
        g_csr[pos] = ((unsigned long long)__float_as_uint(v) << 32) | (unsigned)c;
    }
}

// ---------------------------------------------------------------------------
// Pull rows from the shared atomic queue: accumulate val*x[col] in registers.
__device__ __forceinline__ void pull_rows(const float4* __restrict__ x4,
                                          int n, int lane) {
    while (true) {
        int p;
        if (lane == 0) p = atomicAdd(&g_rowcur, 8);
        p = __shfl_sync(0xffffffffu, p, 0);
        if (p >= n) break;
        const int pe = min(p + 8, n);
        for (int r = p; r < pe; r++) {
            const int beg = __ldg(g_off + r);
            const int end = __ldg(g_off + r + 1);
            float4 acc = make_float4(0.f, 0.f, 0.f, 0.f);
            int j = beg;
            // 8-deep batches: 8 independent LDG.128 gathers in flight
            for (; j + 8 <= end; j += 8) {
                unsigned long long pp[8];
#pragma unroll
                for (int i = 0; i < 8; i++) pp[i] = __ldg(g_csr + j + i);
                float4 a[8];
#pragma unroll
                for (int i = 0; i < 8; i++)
                    a[i] = __ldg(x4 + (size_t)(unsigned)pp[i] * 32 + lane);
#pragma unroll
                for (int i = 0; i < 8; i++) {
                    float v = __uint_as_float((unsigned)(pp[i] >> 32));
                    acc.x += v * a[i].x; acc.y += v * a[i].y;
                    acc.z += v * a[i].z; acc.w += v * a[i].w;
                }
            }
            for (; j + 2 <= end; j += 2) {
                unsigned long long p0 = __ldg(g_csr + j);
                unsigned long long p1 = __ldg(g_csr + j + 1);
                float4 a = __ldg(x4 + (size_t)(unsigned)p0 * 32 + lane);
                float4 b = __ldg(x4 + (size_t)(unsigned)p1 * 32 + lane);
                float v0 = __uint_as_float((unsigned)(p0 >> 32));
                float v1 = __uint_as_float((unsigned)(p1 >> 32));
                acc.x += v0 * a.x; acc.y += v0 * a.y;
                acc.z += v0 * a.z; acc.w += v0 * a.w;
                acc.x += v1 * b.x; acc.y += v1 * b.y;
                acc.z += v1 * b.z; acc.w += v1 * b.w;
            }
            for (; j < end; j++) {
                unsigned long long pq = __ldg(g_csr + j);
                float4 a = __ldg(x4 + (size_t)(unsigned)pq * 32 + lane);
                float v = __uint_as_float((unsigned)(pq >> 32));
                acc.x += v * a.x; acc.y += v * a.y;
                acc.z += v * a.z; acc.w += v * a.w;
            }
            reinterpret_cast<float4*>(g_agg)[(size_t)r * 32 + lane] = acc;
        }
    }
}

// ---------------------------------------------------------------------------
// Packed fp32x2 FMA (sm_103a): d = a * b + d
#define FMA2(d, a, b) \
    asm("fma.rn.f32x2 %0, %1, %2, %0;" : "+l"(d) : "l"(a), "l"(b))

__device__ __forceinline__ unsigned long long splat2(float v) {
    unsigned long long r;
    asm("mov.b64 %0, {%1, %1};" : "=l"(r) : "f"(v));
    return r;
}

__device__ __forceinline__ float2 unpack2(unsigned long long p) {
    float2 r;
    asm("mov.b64 {%0, %1}, %2;" : "=f"(r.x), "=f"(r.y) : "l"(p));
    return r;
}

// GEMM of one warp's 8 rows x 128 cols slice against a 128x128 smem weight.
// Arow: smem rows base (this warp), row stride 128 floats.
// Writes relu(acc+bias) to out half (outp already offset by half*128).
__device__ __forceinline__ void gemm_8rows(const float* __restrict__ Arow,
                                           const float* __restrict__ Wh,
                                           float4 bb, float* __restrict__ outp,
                                           int gr0, int n, int c0) {
    unsigned long long acc[8][2];
#pragma unroll
    for (int r = 0; r < 8; r++) { acc[r][0] = 0ull; acc[r][1] = 0ull; }

    for (int k = 0; k < D; k += 4) {
        float4 xr[8];
#pragma unroll
        for (int r = 0; r < 8; r++)
            xr[r] = *reinterpret_cast<const float4*>(Arow + r * D + k);
#pragma unroll
        for (int kk = 0; kk < 4; kk++) {
            ulonglong2 wv = *reinterpret_cast<const ulonglong2*>(
                Wh + (k + kk) * D + c0);
#pragma unroll
            for (int r = 0; r < 8; r++) {
                float xv = reinterpret_cast<const float*>(&xr[r])[kk];
                unsigned long long xs = splat2(xv);
                FMA2(acc[r][0], xs, wv.x);
                FMA2(acc[r][1], xs, wv.y);
            }
        }
    }
#pragma unroll
    for (int r = 0; r < 8; r++) {
        int gr = gr0 + r;
        if (gr < n) {
            float2 p0 = unpack2(acc[r][0]);
            float2 p1 = unpack2(acc[r][1]);
            float4 o;
            o.x = fmaxf(p0.x + bb.x, 0.f);
            o.y = fmaxf(p0.y + bb.y, 0.f);
            o.z = fmaxf(p1.x + bb.z, 0.f);
            o.w = fmaxf(p1.y + bb.w, 0.f);
            __stcs(reinterpret_cast<float4*>(outp + (size_t)gr * 256 + c0), o);
        }
    }
}

// Shared: sW (Wl|Wn, 128KB) + sT tile buffer (32KB: 64 rows x 128 floats)
#define SMEM_BYTES ((2 * D * D + 64 * D) * 4)

__global__ void __launch_bounds__(256, 1)
mega_kernel(const float* __restrict__ x,
            const float* __restrict__ Wl,
            const float* __restrict__ bl,
            const float* __restrict__ Wn,
            const float* __restrict__ bn,
            float* __restrict__ out,
            int n) {
    extern __shared__ float sm[];
    float* sW = sm;                 // 2*128*128 floats
    float* sT = sm + 2 * D * D;     // 64*128 floats

    const int tid = threadIdx.x;
    const int lane = tid & 31;
    const int w = tid >> 5;
    const int c0 = lane * 4;
    const float4* x4 = reinterpret_cast<const float4*>(x);

    // Load both weight matrices into shared
    {
        const float4* wl4 = reinterpret_cast<const float4*>(Wl);
        const float4* wn4 = reinterpret_cast<const float4*>(Wn);
        float4* sW4 = reinterpret_cast<float4*>(sW);
        for (int i = tid; i < D * D / 4; i += 256) {
            sW4[i] = wl4[i];
            sW4[D * D / 4 + i] = wn4[i];
        }
    }
    __syncthreads();

    // ---------------- phase 1: local GEMM (warps 0-3) || pull (warps 4-7) ---
    if (w < 4) {
        float4 bb = *reinterpret_cast<const float4*>(bl + c0);
        const int ntiles1 = (n + 31) / 32;
        for (int t = blockIdx.x; t < ntiles1; t += gridDim.x) {
            const int row0 = t * 32;
            asm volatile("bar.sync 1, 128;" ::: "memory");
            // 128 threads load 32x128 x-tile (zero-padded tail)
            {
                float4* sT4 = reinterpret_cast<float4*>(sT);
                float4 z = make_float4(0.f, 0.f, 0.f, 0.f);
                for (int i = tid; i < 32 * 32; i += 128) {
                    int r = i >> 5, kk = i & 31;
                    int gr = row0 + r;
                    sT4[i] = (gr < n) ? x4[(size_t)gr * 32 + kk] : z;
                }
            }
            asm volatile("bar.sync 1, 128;" ::: "memory");
            gemm_8rows(sT + (w * 8) * D, sW, bb, out, row0 + w * 8, n, c0);
        }
        // done with local tiles -> help the pull queue
        pull_rows(x4, n, lane);
    } else {
        pull_rows(x4, n, lane);
    }
    __syncthreads();

    // ---------------- device-wide barrier (148 co-resident CTAs) ------------
    if (tid == 0) {
        __threadfence();
        atomicAdd(&g_bar, 1);
        int nb = (int)gridDim.x;
        while (true) {
            int v;
            asm volatile("ld.global.acquire.gpu.b32 %0, [%1];"
                         : "=r"(v) : "l"(&g_bar));
            if (v >= nb) break;
            __nanosleep(128);
        }
    }
    __syncthreads();

    // ---------------- phase 2: neigh GEMM (all 8 warps, 64-row tiles) -------
    {
        float4 bb = *reinterpret_cast<const float4*>(bn + c0);
        const float4* a4 = reinterpret_cast<const float4*>(g_agg);
        const int ntiles2 = (n + 63) / 64;
        for (int t = blockIdx.x; t < ntiles2; t += gridDim.x) {
            const int row0 = t * 64;
            __syncthreads();
            {
                float4* sT4 = reinterpret_cast<float4*>(sT);
                float4 z = make_float4(0.f, 0.f, 0.f, 0.f);
                for (int i = tid; i < 64 * 32; i += 256) {
                    int r = i >> 5, kk = i & 31;
                    int gr = row0 + r;
                    sT4[i] = (gr < n) ? a4[(size_t)gr * 32 + kk] : z;
                }
            }
            __syncthreads();
            gemm_8rows(sT + (w * 8) * D, sW + D * D, bb, out + D,
                       row0 + w * 8, n, c0);
        }
    }
}

// ---------------------------------------------------------------------------
extern "C" void kernel_launch(void* const* d_in, const int* in_sizes, int n_in,
                              void* d_out, int out_size) {
    const float* x  = (const float*)d_in[0];
    const int* erow = (const int*)d_in[1];
    const int* ecol = (const int*)d_in[2];
    const float* ev = (const float*)d_in[3];
    const float* Wl = (const float*)d_in[4];
    const float* bl = (const float*)d_in[5];
    const float* Wn = (const float*)d_in[6];
    const float* bn = (const float*)d_in[7];

    const int n = in_sizes[0] / D;   // nodes (100000)
    const int E = in_sizes[1];       // edges (1600000)
    const int nb = (n + 255) / 256;  // 391 <= 512

    // CSR build (per call; no caching allowed)
    k_zero_deg<<<256, 256>>>(n);
    k_hist<<<1024, 256>>>(erow, E);
    k_partial<<<nb, 256>>>(n);
    k_scan<<<1, 512>>>(nb);
    k_offsets<<<nb, 256>>>(n);
    k_bin<<<1024, 256>>>(erow, ecol, ev, E);

    // Mega kernel: phase1 (pull || local GEMM), barrier, phase2 (neigh GEMM)
    cudaFuncSetAttribute(mega_kernel,
                         cudaFuncAttributeMaxDynamicSharedMemorySize, SMEM_BYTES);
    mega_kernel<<<148, 256, SMEM_BYTES>>>(x, Wl, bl, Wn, bn, (float*)d_out, n);
}